// round 1
// baseline (speedup 1.0000x reference)
#include <cuda_runtime.h>
#include <cuda_bf16.h>
#include <math.h>

// Problem constants (fixed by dataset)
#define B_      64
#define IC_     2048
#define ID_     16
#define NC_     64
#define CD_     16
#define K_      1024          // NC_*CD_
#define BSTRIDE ((size_t)IC_ * K_)   // stride between batches in u_hat (floats)

// ---------------- device scratch (allocation-free rule: device globals) ----
__device__ float g_uhat[(size_t)B_ * IC_ * K_];   // 512 MB  [b][i][k]
__device__ float g_s[B_ * K_];                    // s accumulator
__device__ float g_v0[B_ * K_];
__device__ float g_v1[B_ * K_];

// ---------------- f32x2 packed-FMA helpers (Blackwell) ---------------------
__device__ __forceinline__ unsigned long long pack2(float lo, float hi) {
    unsigned long long r;
    asm("mov.b64 %0, {%1, %2};" : "=l"(r) : "f"(lo), "f"(hi));
    return r;
}
__device__ __forceinline__ unsigned long long fma2(unsigned long long a,
                                                   unsigned long long b,
                                                   unsigned long long c) {
    unsigned long long d;
    asm("fma.rn.f32x2 %0, %1, %2, %3;" : "=l"(d) : "l"(a), "l"(b), "l"(c));
    return d;
}
__device__ __forceinline__ void unpack2(unsigned long long v, float& lo, float& hi) {
    asm("mov.b64 {%0, %1}, %2;" : "=f"(lo), "=f"(hi) : "l"(v));
}

// ---------------- kernel 0: s <- bias (broadcast over b) -------------------
__global__ __launch_bounds__(1024) void k_init_s(const float* __restrict__ bias) {
    int idx = blockIdx.x * 1024 + threadIdx.x;   // 64 blocks -> 65536
    g_s[idx] = bias[idx & (K_ - 1)];
}

// ---------------- kernel 1: u_hat projection -------------------------------
// grid = IC_ CTAs (one input capsule i each), 256 threads.
// Each CTA: loads x[:, i, :] (1 KB) to smem, streams W[i] (64 KB) once,
// computes u_hat[b, i, k] for all b,k. Two batches packed per f32x2 lane.
__global__ __launch_bounds__(256) void k_project(const float* __restrict__ x,
                                                 const float* __restrict__ W) {
    const int i = blockIdx.x;
    const int t = threadIdx.x;

    __shared__ float xs[B_ * ID_];                 // 4 KB
    __shared__ unsigned long long xsp[(B_ / 2) * ID_]; // 4 KB: (b2,b2+1) pairs

    for (int idx = t; idx < B_ * ID_; idx += 256) {
        int b = idx >> 4, j = idx & 15;
        xs[idx] = x[((size_t)b * IC_ + i) * ID_ + j];
    }
    __syncthreads();
    for (int idx = t; idx < (B_ / 2) * ID_; idx += 256) {
        int bp = idx >> 4, j = idx & 15;
        xsp[idx] = pack2(xs[(2 * bp) * ID_ + j], xs[(2 * bp + 1) * ID_ + j]);
    }
    __syncthreads();

    const float* Wi = W + (size_t)i * ID_ * K_;
    float* up = g_uhat + (size_t)i * K_;

    #pragma unroll 1
    for (int it = 0; it < 4; it++) {
        const int kk = it * 256 + t;
        // broadcast-packed W column (16 values for this k)
        unsigned long long wb[ID_];
        #pragma unroll
        for (int j = 0; j < ID_; j++) {
            float wv = Wi[j * K_ + kk];
            wb[j] = pack2(wv, wv);
        }
        #pragma unroll 2
        for (int bp = 0; bp < B_ / 2; bp++) {
            const ulonglong2* xv = (const ulonglong2*)&xsp[bp * ID_];
            unsigned long long acc = 0ull;
            #pragma unroll
            for (int jq = 0; jq < ID_ / 2; jq++) {
                ulonglong2 xv2 = xv[jq];
                acc = fma2(xv2.x, wb[2 * jq + 0], acc);
                acc = fma2(xv2.y, wb[2 * jq + 1], acc);
            }
            float uA, uB;
            unpack2(acc, uA, uB);
            up[(size_t)(2 * bp)     * BSTRIDE + kk] = uA;
            up[(size_t)(2 * bp + 1) * BSTRIDE + kk] = uB;
        }
    }
}

// ---------------- kernel 2: s0 += (1/64) * sum_i u_hat ---------------------
// grid = (8 i-splits, 64 b), 256 threads; thread t owns k = 4t..4t+3.
__global__ __launch_bounds__(256) void k_s0() {
    const int b = blockIdx.y, sp = blockIdx.x, t = threadIdx.x;
    const float4* base =
        (const float4*)(g_uhat + ((size_t)b * IC_ + (size_t)sp * 256) * K_);
    float4 acc = make_float4(0.f, 0.f, 0.f, 0.f);
    #pragma unroll 4
    for (int i = 0; i < 256; i++) {
        float4 u = base[(size_t)i * (K_ / 4) + t];
        acc.x += u.x; acc.y += u.y; acc.z += u.z; acc.w += u.w;
    }
    const float sc = 1.0f / 64.0f;
    float* p = g_s + b * K_ + t * 4;
    atomicAdd(p + 0, acc.x * sc);
    atomicAdd(p + 1, acc.y * sc);
    atomicAdd(p + 2, acc.z * sc);
    atomicAdd(p + 3, acc.w * sc);
}

// ---------------- kernel 3: squash(s) -> dst -------------------------------
// grid = 64 (b), block = 1024 (k). 16-lane shuffle reduce per capsule.
__global__ __launch_bounds__(1024) void k_squash(int sel, float* __restrict__ outbuf) {
    const int b = blockIdx.x, t = threadIdx.x;
    float sv = g_s[b * K_ + t];
    float sq = sv * sv;
    #pragma unroll
    for (int off = 8; off >= 1; off >>= 1)
        sq += __shfl_xor_sync(0xffffffffu, sq, off, 16);
    float tt = sq + 1e-7f;
    float norm = sqrtf(tt);
    float f = tt / (1.0f + tt) / norm;
    float* dst = (sel == 0) ? g_v0 : (sel == 1 ? g_v1 : outbuf);
    dst[b * K_ + t] = f * sv;
}

// ---------------- kernel 4: one routing pass -------------------------------
// grid = (32 i-blocks of 64, 64 b), 256 threads.
// thread t: n = t>>2, quad member g = t&3, owns k = n*16 + 4g .. +3  (== 4t)
// For each i: agreement = u.v (quad+warp reduce), block softmax over n,
// accumulate c*u into register partials; one atomic flush at the end.
// SECOND pass logits: b2 = u.v0 + u.v1 = u.(v0+v1)  -> fold into vsum.
template <bool SECOND>
__global__ __launch_bounds__(256) void k_route() {
    const int b = blockIdx.y;
    const int i0 = blockIdx.x * 64;
    const int t = threadIdx.x;
    const int lane = t & 31;
    const int w = t >> 5;

    __shared__ float vsum[K_];
    __shared__ float redM[2][8];
    __shared__ float redS[2][8];

    for (int idx = t; idx < K_; idx += 256) {
        float v = g_v0[b * K_ + idx];
        if (SECOND) v += g_v1[b * K_ + idx];
        vsum[idx] = v;
    }
    __syncthreads();

    const float4 vv = *(const float4*)&vsum[t * 4];
    const float4* urow =
        (const float4*)(g_uhat + ((size_t)b * IC_ + i0) * K_);

    float4 acc = make_float4(0.f, 0.f, 0.f, 0.f);
    float4 u_next = urow[t];                       // prefetch i0
    #pragma unroll 1
    for (int il = 0; il < 64; il++) {
        float4 u = u_next;
        if (il < 63) u_next = urow[(il + 1) * (K_ / 4) + t];

        // agreement partial over this thread's 4 dims
        float a = u.x * vv.x + u.y * vv.y + u.z * vv.z + u.w * vv.w;
        // reduce across the quad (16 dims total)
        a += __shfl_xor_sync(0xffffffffu, a, 1);
        a += __shfl_xor_sync(0xffffffffu, a, 2);

        // block softmax over the 64 n's (8 distinct per warp, quad-uniform)
        float m = a;
        m = fmaxf(m, __shfl_xor_sync(0xffffffffu, m, 4));
        m = fmaxf(m, __shfl_xor_sync(0xffffffffu, m, 8));
        m = fmaxf(m, __shfl_xor_sync(0xffffffffu, m, 16));
        const int p = il & 1;
        if (lane == 0) redM[p][w] = m;
        __syncthreads();
        float M = redM[p][0];
        #pragma unroll
        for (int q = 1; q < 8; q++) M = fmaxf(M, redM[p][q]);

        float e = __expf(a - M);
        float zs = e;  // xor 4/8/16 sums the 8 distinct values exactly once
        zs += __shfl_xor_sync(0xffffffffu, zs, 4);
        zs += __shfl_xor_sync(0xffffffffu, zs, 8);
        zs += __shfl_xor_sync(0xffffffffu, zs, 16);
        if (lane == 0) redS[p][w] = zs;
        __syncthreads();
        float Z = redS[p][0];
        #pragma unroll
        for (int q = 1; q < 8; q++) Z += redS[p][q];

        float c = e / Z;
        acc.x += c * u.x; acc.y += c * u.y; acc.z += c * u.z; acc.w += c * u.w;
    }

    float* sp = g_s + b * K_ + t * 4;
    atomicAdd(sp + 0, acc.x);
    atomicAdd(sp + 1, acc.y);
    atomicAdd(sp + 2, acc.z);
    atomicAdd(sp + 3, acc.w);
}

// ---------------- launcher -------------------------------------------------
extern "C" void kernel_launch(void* const* d_in, const int* in_sizes, int n_in,
                              void* d_out, int out_size) {
    const float* x    = (const float*)d_in[0];   // [64,2048,16]
    const float* W    = (const float*)d_in[1];   // [2048,16,1024]
    const float* bias = (const float*)d_in[2];   // [64,16] -> [1024]
    float* out = (float*)d_out;                  // [64,64,16]

    // iter 0: s0 = mean_i u_hat + bias ; v0 = squash(s0)
    k_init_s<<<64, 1024>>>(bias);
    k_project<<<IC_, 256>>>(x, W);
    k_s0<<<dim3(8, B_), 256>>>();
    k_squash<<<B_, 1024>>>(0, out);

    // iter 1: b1 = u.v0 ; s1 = sum_i softmax(b1)*u + bias ; v1 = squash(s1)
    k_init_s<<<64, 1024>>>(bias);
    k_route<false><<<dim3(IC_ / 64, B_), 256>>>();
    k_squash<<<B_, 1024>>>(1, out);

    // iter 2: b2 = u.v0 + u.v1 ; s2 likewise ; v2 = output
    k_init_s<<<64, 1024>>>(bias);
    k_route<true><<<dim3(IC_ / 64, B_), 256>>>();
    k_squash<<<B_, 1024>>>(2, out);
}

// round 2
// speedup vs baseline: 1.2417x; 1.2417x over previous
#include <cuda_runtime.h>
#include <math.h>

// Problem constants
#define B_  64
#define IC_ 2048
#define ID_ 16
#define K_  1024           // NC*CD = 64*16

// ---------------- device scratch (no allocations allowed) ------------------
__device__ float g_uhat[(size_t)B_ * IC_ * K_];   // 512 MB  [b][i][k]
__device__ float g_s[3][B_ * K_];                 // s per routing iteration
__device__ float g_v0[B_ * K_];
__device__ float g_v1[B_ * K_];

// ---------------- f32x2 packed helpers (Blackwell) -------------------------
__device__ __forceinline__ unsigned long long pack2(float lo, float hi) {
    unsigned long long r;
    asm("mov.b64 %0, {%1, %2};" : "=l"(r) : "f"(lo), "f"(hi));
    return r;
}
__device__ __forceinline__ unsigned long long fma2(unsigned long long a,
                                                   unsigned long long b,
                                                   unsigned long long c) {
    unsigned long long d;
    asm("fma.rn.f32x2 %0, %1, %2, %3;" : "=l"(d) : "l"(a), "l"(b), "l"(c));
    return d;
}
__device__ __forceinline__ unsigned long long add2(unsigned long long a,
                                                   unsigned long long b) {
    unsigned long long d;
    asm("add.rn.f32x2 %0, %1, %2;" : "=l"(d) : "l"(a), "l"(b));
    return d;
}
__device__ __forceinline__ void unpack2(unsigned long long v, float& lo, float& hi) {
    asm("mov.b64 {%0, %1}, %2;" : "=f"(lo), "=f"(hi) : "l"(v));
}

// ---------------- kernel 0: s[0..2] <- bias broadcast ----------------------
__global__ __launch_bounds__(1024) void k_init(const float* __restrict__ bias) {
    const int blk = blockIdx.x;                    // 192 blocks: 3 bufs x 64 b
    g_s[blk >> 6][(blk & 63) * K_ + threadIdx.x] = bias[threadIdx.x];
}

// ---------------- kernel 1: projection + fused iter-0 mean -----------------
// grid = (2 kchunks, 2 bgroups, 64 isegs) = 256 CTAs, 256 threads.
// thread t owns k-pair (kbase+2t, kbase+2t+1) as one f32x2 lane.
// Register acc[32] holds sum over this CTA's 32 i for each b; one atomic flush.
#define KC    512
#define BG    32
#define ISEG  32
__global__ __launch_bounds__(256, 2) void k_project(const float* __restrict__ x,
                                                    const float* __restrict__ W) {
    const int t     = threadIdx.x;
    const int kbase = blockIdx.x * KC;
    const int bbase = blockIdx.y * BG;
    const int i0    = blockIdx.z * ISEG;
    const int k2    = kbase + 2 * t;

    __shared__ float xs[BG][16][ID_];              // 32 KB, reused per half

    unsigned long long acc[BG];
    #pragma unroll
    for (int b = 0; b < BG; b++) acc[b] = 0ull;

    for (int half = 0; half < 2; half++) {
        __syncthreads();                           // protect previous xs use
        // load x[bbase..+32, i0+half*16 .. +16, :] : 2048 float4
        for (int r = t; r < 2048; r += 256) {
            const int b   = r >> 6;
            const int rem = r & 63;
            const int ii  = rem >> 2, q = rem & 3;
            const float4 v = *(const float4*)(x +
                ((size_t)(bbase + b) * IC_ + (i0 + half * 16 + ii)) * ID_ + q * 4);
            *(float4*)&xs[b][ii][q * 4] = v;
        }
        __syncthreads();

        #pragma unroll 1
        for (int ii = 0; ii < 16; ii++) {
            const int i = i0 + half * 16 + ii;
            const float* Wi = W + (size_t)i * ID_ * K_ + k2;
            unsigned long long w[16];
            #pragma unroll
            for (int j = 0; j < 16; j++)
                w[j] = *(const unsigned long long*)(Wi + (size_t)j * K_);

            #pragma unroll 4
            for (int b = 0; b < BG; b++) {
                unsigned long long a = 0ull;
                #pragma unroll
                for (int jq = 0; jq < 4; jq++) {
                    const float4 xv = *(const float4*)&xs[b][ii][jq * 4];
                    a = fma2(w[jq * 4 + 0], pack2(xv.x, xv.x), a);
                    a = fma2(w[jq * 4 + 1], pack2(xv.y, xv.y), a);
                    a = fma2(w[jq * 4 + 2], pack2(xv.z, xv.z), a);
                    a = fma2(w[jq * 4 + 3], pack2(xv.w, xv.w), a);
                }
                *(unsigned long long*)(g_uhat +
                    ((size_t)(bbase + b) * IC_ + i) * K_ + k2) = a;
                acc[b] = add2(acc[b], a);
            }
        }
    }

    const float sc = 1.0f / 64.0f;                 // softmax(0) weight
    #pragma unroll 4
    for (int b = 0; b < BG; b++) {
        float lo, hi;
        unpack2(acc[b], lo, hi);
        float* sp = g_s[0] + (bbase + b) * K_ + k2;
        atomicAdd(sp,     lo * sc);
        atomicAdd(sp + 1, hi * sc);
    }
}

// ---------------- kernel 2: squash(s[it]) -> v0/v1/out ---------------------
__global__ __launch_bounds__(1024) void k_squash(int it, float* __restrict__ outbuf) {
    const int b = blockIdx.x, t = threadIdx.x;
    float sv = g_s[it][b * K_ + t];
    float sq = sv * sv;
    #pragma unroll
    for (int off = 8; off >= 1; off >>= 1)
        sq += __shfl_xor_sync(0xffffffffu, sq, off, 16);
    const float tt = sq + 1e-7f;
    const float norm = sqrtf(tt);
    const float f = tt / (1.0f + tt) / norm;
    float* dst = (it == 0) ? g_v0 : (it == 1 ? g_v1 : outbuf);
    dst[b * K_ + t] = f * sv;
}

// ---------------- kernel 3: barrier-free routing pass ----------------------
// grid = (16, 64 b), block = 64 (2 autonomous warps). Warp task = 64 i's.
// Lane owns capsules n0=lane, n1=lane+32 (full 16-dim rows in registers).
// Per i: stream one 4KB u row, warp-shuffle softmax over 64 n, accumulate c*u.
// SECOND pass logits: b2 = u.(v0+v1).
template <bool SECOND>
__global__ __launch_bounds__(64) void k_route() {
    const int b    = blockIdx.y;
    const int wt   = blockIdx.x * 2 + (threadIdx.x >> 5);
    const int lane = threadIdx.x & 31;
    const int i0   = wt * 64;
    const int n0   = lane, n1 = lane + 32;

    float4 vA[4], vB[4];
    {
        const float4* vp = (const float4*)(g_v0 + b * K_);
        #pragma unroll
        for (int q = 0; q < 4; q++) { vA[q] = vp[n0 * 4 + q]; vB[q] = vp[n1 * 4 + q]; }
        if (SECOND) {
            const float4* vq = (const float4*)(g_v1 + b * K_);
            #pragma unroll
            for (int q = 0; q < 4; q++) {
                float4 a = vq[n0 * 4 + q];
                vA[q].x += a.x; vA[q].y += a.y; vA[q].z += a.z; vA[q].w += a.w;
                float4 c = vq[n1 * 4 + q];
                vB[q].x += c.x; vB[q].y += c.y; vB[q].z += c.z; vB[q].w += c.w;
            }
        }
    }

    const float4* up = (const float4*)(g_uhat + ((size_t)b * IC_ + i0) * K_);
    float4 aA[4], aB[4];
    #pragma unroll
    for (int q = 0; q < 4; q++) {
        aA[q] = make_float4(0.f, 0.f, 0.f, 0.f);
        aB[q] = make_float4(0.f, 0.f, 0.f, 0.f);
    }

    #pragma unroll 1
    for (int i = 0; i < 64; i++) {
        const float4* row = up + (size_t)i * (K_ / 4);
        float4 uA[4], uB[4];
        #pragma unroll
        for (int q = 0; q < 4; q++) { uA[q] = row[n0 * 4 + q]; uB[q] = row[n1 * 4 + q]; }

        float a0 = 0.f, a1 = 0.f;
        #pragma unroll
        for (int q = 0; q < 4; q++) {
            a0 = fmaf(uA[q].x, vA[q].x, a0); a0 = fmaf(uA[q].y, vA[q].y, a0);
            a0 = fmaf(uA[q].z, vA[q].z, a0); a0 = fmaf(uA[q].w, vA[q].w, a0);
            a1 = fmaf(uB[q].x, vB[q].x, a1); a1 = fmaf(uB[q].y, vB[q].y, a1);
            a1 = fmaf(uB[q].z, vB[q].z, a1); a1 = fmaf(uB[q].w, vB[q].w, a1);
        }

        float m = fmaxf(a0, a1);
        #pragma unroll
        for (int off = 16; off >= 1; off >>= 1)
            m = fmaxf(m, __shfl_xor_sync(0xffffffffu, m, off));
        const float e0 = __expf(a0 - m);
        const float e1 = __expf(a1 - m);
        float z = e0 + e1;
        #pragma unroll
        for (int off = 16; off >= 1; off >>= 1)
            z += __shfl_xor_sync(0xffffffffu, z, off);
        const float rz = __fdividef(1.0f, z);
        const float c0 = e0 * rz, c1 = e1 * rz;

        #pragma unroll
        for (int q = 0; q < 4; q++) {
            aA[q].x = fmaf(c0, uA[q].x, aA[q].x); aA[q].y = fmaf(c0, uA[q].y, aA[q].y);
            aA[q].z = fmaf(c0, uA[q].z, aA[q].z); aA[q].w = fmaf(c0, uA[q].w, aA[q].w);
            aB[q].x = fmaf(c1, uB[q].x, aB[q].x); aB[q].y = fmaf(c1, uB[q].y, aB[q].y);
            aB[q].z = fmaf(c1, uB[q].z, aB[q].z); aB[q].w = fmaf(c1, uB[q].w, aB[q].w);
        }
    }

    float* sp = g_s[SECOND ? 2 : 1] + b * K_;
    #pragma unroll
    for (int q = 0; q < 4; q++) {
        atomicAdd(sp + n0 * 16 + q * 4 + 0, aA[q].x);
        atomicAdd(sp + n0 * 16 + q * 4 + 1, aA[q].y);
        atomicAdd(sp + n0 * 16 + q * 4 + 2, aA[q].z);
        atomicAdd(sp + n0 * 16 + q * 4 + 3, aA[q].w);
        atomicAdd(sp + n1 * 16 + q * 4 + 0, aB[q].x);
        atomicAdd(sp + n1 * 16 + q * 4 + 1, aB[q].y);
        atomicAdd(sp + n1 * 16 + q * 4 + 2, aB[q].z);
        atomicAdd(sp + n1 * 16 + q * 4 + 3, aB[q].w);
    }
}

// ---------------- launcher -------------------------------------------------
extern "C" void kernel_launch(void* const* d_in, const int* in_sizes, int n_in,
                              void* d_out, int out_size) {
    const float* x    = (const float*)d_in[0];   // [64,2048,16]
    const float* W    = (const float*)d_in[1];   // [2048,16,1024]
    const float* bias = (const float*)d_in[2];   // [64,16] -> 1024
    float* out = (float*)d_out;                  // [64,64,16]

    k_init<<<192, 1024>>>(bias);                         // s0,s1,s2 = bias
    k_project<<<dim3(2, 2, 64), 256>>>(x, W);            // u_hat + s0 mean
    k_squash<<<B_, 1024>>>(0, out);                      // v0

    k_route<false><<<dim3(16, B_), 64>>>();              // s1
    k_squash<<<B_, 1024>>>(1, out);                      // v1

    k_route<true><<<dim3(16, B_), 64>>>();               // s2
    k_squash<<<B_, 1024>>>(2, out);                      // v2 -> out
}

// round 3
// speedup vs baseline: 1.4240x; 1.1468x over previous
#include <cuda_runtime.h>
#include <cuda_fp16.h>
#include <math.h>

// Problem constants
#define B_  64
#define IC_ 2048
#define ID_ 16
#define K_  1024           // NC*CD = 64*16

// ---------------- device scratch (no allocations allowed) ------------------
__device__ __half g_uhat[(size_t)B_ * IC_ * K_]; // 256 MB  [b][i][k], fp16
__device__ float  g_s[3][B_ * K_];               // s per routing iteration (fp32)
__device__ float  g_v0[B_ * K_];
__device__ float  g_v1[B_ * K_];

// ---------------- f32x2 packed helpers (Blackwell) -------------------------
__device__ __forceinline__ unsigned long long pack2(float lo, float hi) {
    unsigned long long r;
    asm("mov.b64 %0, {%1, %2};" : "=l"(r) : "f"(lo), "f"(hi));
    return r;
}
__device__ __forceinline__ unsigned long long fma2(unsigned long long a,
                                                   unsigned long long b,
                                                   unsigned long long c) {
    unsigned long long d;
    asm("fma.rn.f32x2 %0, %1, %2, %3;" : "=l"(d) : "l"(a), "l"(b), "l"(c));
    return d;
}
__device__ __forceinline__ unsigned long long add2(unsigned long long a,
                                                   unsigned long long b) {
    unsigned long long d;
    asm("add.rn.f32x2 %0, %1, %2;" : "=l"(d) : "l"(a), "l"(b));
    return d;
}
__device__ __forceinline__ void unpack2(unsigned long long v, float& lo, float& hi) {
    asm("mov.b64 {%0, %1}, %2;" : "=f"(lo), "=f"(hi) : "l"(v));
}

// ---------------- kernel 0: s[0..2] <- bias broadcast ----------------------
__global__ __launch_bounds__(1024) void k_init(const float* __restrict__ bias) {
    const int blk = blockIdx.x;                    // 192 blocks: 3 bufs x 64 b
    g_s[blk >> 6][(blk & 63) * K_ + threadIdx.x] = bias[threadIdx.x];
}

// ---------------- kernel 1: projection + fused iter-0 mean -----------------
// grid = (2 kchunks, 2 bgroups, 64 isegs) = 256 CTAs, 256 threads.
// thread t owns k-pair (kbase+2t, kbase+2t+1) as one f32x2 lane.
// fp32 accumulate; fp16 convert only at the u_hat store. s0 mean stays fp32.
#define KC    512
#define BG    32
#define ISEG  32
__global__ __launch_bounds__(256, 2) void k_project(const float* __restrict__ x,
                                                    const float* __restrict__ W) {
    const int t     = threadIdx.x;
    const int kbase = blockIdx.x * KC;
    const int bbase = blockIdx.y * BG;
    const int i0    = blockIdx.z * ISEG;
    const int k2    = kbase + 2 * t;

    __shared__ float xs[BG][16][ID_];              // 32 KB, reused per half

    unsigned long long acc[BG];
    #pragma unroll
    for (int b = 0; b < BG; b++) acc[b] = 0ull;

    for (int half = 0; half < 2; half++) {
        __syncthreads();                           // protect previous xs use
        for (int r = t; r < 2048; r += 256) {
            const int b   = r >> 6;
            const int rem = r & 63;
            const int ii  = rem >> 2, q = rem & 3;
            const float4 v = *(const float4*)(x +
                ((size_t)(bbase + b) * IC_ + (i0 + half * 16 + ii)) * ID_ + q * 4);
            *(float4*)&xs[b][ii][q * 4] = v;
        }
        __syncthreads();

        #pragma unroll 1
        for (int ii = 0; ii < 16; ii++) {
            const int i = i0 + half * 16 + ii;
            const float* Wi = W + (size_t)i * ID_ * K_ + k2;
            unsigned long long w[16];
            #pragma unroll
            for (int j = 0; j < 16; j++)
                w[j] = *(const unsigned long long*)(Wi + (size_t)j * K_);

            #pragma unroll 4
            for (int b = 0; b < BG; b++) {
                unsigned long long a = 0ull;
                #pragma unroll
                for (int jq = 0; jq < 4; jq++) {
                    const float4 xv = *(const float4*)&xs[b][ii][jq * 4];
                    a = fma2(w[jq * 4 + 0], pack2(xv.x, xv.x), a);
                    a = fma2(w[jq * 4 + 1], pack2(xv.y, xv.y), a);
                    a = fma2(w[jq * 4 + 2], pack2(xv.z, xv.z), a);
                    a = fma2(w[jq * 4 + 3], pack2(xv.w, xv.w), a);
                }
                float lo, hi;
                unpack2(a, lo, hi);
                *(__half2*)(g_uhat +
                    ((size_t)(bbase + b) * IC_ + i) * K_ + k2) =
                    __floats2half2_rn(lo, hi);
                acc[b] = add2(acc[b], a);          // fp32 mean accumulation
            }
        }
    }

    const float sc = 1.0f / 64.0f;                 // softmax(0) weight
    #pragma unroll 4
    for (int b = 0; b < BG; b++) {
        float lo, hi;
        unpack2(acc[b], lo, hi);
        float* sp = g_s[0] + (bbase + b) * K_ + k2;
        atomicAdd(sp,     lo * sc);
        atomicAdd(sp + 1, hi * sc);
    }
}

// ---------------- kernel 2: squash(s[it]) -> v0/v1/out ---------------------
__global__ __launch_bounds__(1024) void k_squash(int it, float* __restrict__ outbuf) {
    const int b = blockIdx.x, t = threadIdx.x;
    float sv = g_s[it][b * K_ + t];
    float sq = sv * sv;
    #pragma unroll
    for (int off = 8; off >= 1; off >>= 1)
        sq += __shfl_xor_sync(0xffffffffu, sq, off, 16);
    const float tt = sq + 1e-7f;
    const float norm = sqrtf(tt);
    const float f = tt / (1.0f + tt) / norm;
    float* dst = (it == 0) ? g_v0 : (it == 1 ? g_v1 : outbuf);
    dst[b * K_ + t] = f * sv;
}

// ---------------- kernel 3: barrier-free routing pass (fp16 u_hat) ---------
// grid = (16, 64 b), block = 128 (4 autonomous warps). Warp task = 32 i's.
// Lane owns capsules n0=lane, n1=lane+32; v rows live in fp32 registers.
// Per i: load 2KB u row (fp16), convert, warp-shuffle softmax over 64 n
// (no max-sub: |logit| < 1), accumulate c*u in fp32; one atomic flush.
template <bool SECOND>
__global__ __launch_bounds__(128, 4) void k_route() {
    const int b    = blockIdx.y;
    const int wt   = blockIdx.x * 4 + (threadIdx.x >> 5);
    const int lane = threadIdx.x & 31;
    const int i0   = wt * 32;

    float vA[16], vB[16];
    {
        const float4* vp = (const float4*)(g_v0 + b * K_);
        #pragma unroll
        for (int q = 0; q < 4; q++) {
            float4 a = vp[lane * 4 + q];
            vA[4 * q] = a.x; vA[4 * q + 1] = a.y; vA[4 * q + 2] = a.z; vA[4 * q + 3] = a.w;
            float4 c = vp[(lane + 32) * 4 + q];
            vB[4 * q] = c.x; vB[4 * q + 1] = c.y; vB[4 * q + 2] = c.z; vB[4 * q + 3] = c.w;
        }
        if (SECOND) {
            const float4* vq = (const float4*)(g_v1 + b * K_);
            #pragma unroll
            for (int q = 0; q < 4; q++) {
                float4 a = vq[lane * 4 + q];
                vA[4 * q] += a.x; vA[4 * q + 1] += a.y; vA[4 * q + 2] += a.z; vA[4 * q + 3] += a.w;
                float4 c = vq[(lane + 32) * 4 + q];
                vB[4 * q] += c.x; vB[4 * q + 1] += c.y; vB[4 * q + 2] += c.z; vB[4 * q + 3] += c.w;
            }
        }
    }

    const uint4* base = (const uint4*)(g_uhat + ((size_t)b * IC_ + i0) * K_);
    float sA[16], sB[16];
    #pragma unroll
    for (int q = 0; q < 16; q++) { sA[q] = 0.f; sB[q] = 0.f; }

    #pragma unroll 1
    for (int i = 0; i < 32; i++) {
        const uint4* row = base + (size_t)i * (K_ / 8);
        uint4 rA0 = row[lane * 2], rA1 = row[lane * 2 + 1];
        uint4 rB0 = row[64 + lane * 2], rB1 = row[64 + lane * 2 + 1];

        float uA[16], uB[16];
        {
            const __half2* hA0 = (const __half2*)&rA0;
            const __half2* hA1 = (const __half2*)&rA1;
            const __half2* hB0 = (const __half2*)&rB0;
            const __half2* hB1 = (const __half2*)&rB1;
            #pragma unroll
            for (int w = 0; w < 4; w++) {
                float2 f;
                f = __half22float2(hA0[w]); uA[2 * w] = f.x; uA[2 * w + 1] = f.y;
                f = __half22float2(hA1[w]); uA[8 + 2 * w] = f.x; uA[8 + 2 * w + 1] = f.y;
                f = __half22float2(hB0[w]); uB[2 * w] = f.x; uB[2 * w + 1] = f.y;
                f = __half22float2(hB1[w]); uB[8 + 2 * w] = f.x; uB[8 + 2 * w + 1] = f.y;
            }
        }

        float a0 = 0.f, a1 = 0.f;
        #pragma unroll
        for (int q = 0; q < 16; q++) {
            a0 = fmaf(uA[q], vA[q], a0);
            a1 = fmaf(uB[q], vB[q], a1);
        }

        // softmax over 64 n without max-sub (|a| bounded well below exp range)
        const float e0 = __expf(a0);
        const float e1 = __expf(a1);
        float z = e0 + e1;
        #pragma unroll
        for (int off = 16; off >= 1; off >>= 1)
            z += __shfl_xor_sync(0xffffffffu, z, off);
        const float rz = __fdividef(1.0f, z);
        const float c0 = e0 * rz, c1 = e1 * rz;

        #pragma unroll
        for (int q = 0; q < 16; q++) {
            sA[q] = fmaf(c0, uA[q], sA[q]);
            sB[q] = fmaf(c1, uB[q], sB[q]);
        }
    }

    float* sp = g_s[SECOND ? 2 : 1] + b * K_;
    #pragma unroll
    for (int q = 0; q < 16; q++) {
        atomicAdd(sp + lane * 16 + q, sA[q]);
        atomicAdd(sp + (lane + 32) * 16 + q, sB[q]);
    }
}

// ---------------- launcher -------------------------------------------------
extern "C" void kernel_launch(void* const* d_in, const int* in_sizes, int n_in,
                              void* d_out, int out_size) {
    const float* x    = (const float*)d_in[0];   // [64,2048,16]
    const float* W    = (const float*)d_in[1];   // [2048,16,1024]
    const float* bias = (const float*)d_in[2];   // [64,16] -> 1024
    float* out = (float*)d_out;                  // [64,64,16]

    k_init<<<192, 1024>>>(bias);                         // s0,s1,s2 = bias
    k_project<<<dim3(2, 2, 64), 256>>>(x, W);            // u_hat(fp16) + s0 mean
    k_squash<<<B_, 1024>>>(0, out);                      // v0

    k_route<false><<<dim3(16, B_), 128>>>();             // s1
    k_squash<<<B_, 1024>>>(1, out);                      // v1

    k_route<true><<<dim3(16, B_), 128>>>();              // s2
    k_squash<<<B_, 1024>>>(2, out);                      // v2 -> out
}